// round 2
// baseline (speedup 1.0000x reference)
#include <cuda_runtime.h>
#include <cuda_bf16.h>
#include <math.h>
#include <stdint.h>

// Problem constants (fixed shapes for this bench)
#define BB 4
#define PP 256
#define CC 151
#define RTOT 51
#define RR 50                 // r = 1..50
#define CELLS (CC * RR)       // 7550 per direction
#define G2OFF CELLS
#define GPAD (2 * CELLS)      // 15100 : zero pad slot
#define GTOT (GPAD + 4)       // 15104 floats
#define LSTRIDE 1600          // per-c list capacity (mean ~755, ~31 sigma headroom)

// Static device scratch (no allocation allowed)
__device__ unsigned short g_list[CC * LSTRIDE];   // bank-staggered sparse lists per c
__device__ int            g_cnt[CC];              // padded (multiple of 8) list lengths
__device__ int            g_bstart[BB][CC + 1];   // label bucket offsets per image
__device__ int            g_perm[BB][PP];         // p's sorted by label per image
__device__ float          g_loss[BB * PP];        // per-(b,q) losses
__device__ int            g_counter;              // last-block-done counter

// ---------------------------------------------------------------------------
// Prep kernel. Blocks 0..150: build per-c sparse (l,r) lists from
// relationship_mat, then reorder them so that final position k has smem bank
// ~= (k + c) mod 32  => phase-2 LDS instructions are conflict-free across the
// 32 lanes of a warp (lane c accesses bank (slot + c) mod 32).
// Blocks 151..154: per-image counting sort of p by label (parallel, stable).
// ---------------------------------------------------------------------------
__global__ __launch_bounds__(256) void prep_kernel(const float* __restrict__ mat,
                                                   const int*  __restrict__ labels) {
    const int t   = threadIdx.x;
    const int blk = blockIdx.x;

    if (blk < CC) {
        // ------- list building branch -------
        __shared__ unsigned short sRaw[LSTRIDE];
        __shared__ unsigned short sBank[LSTRIDE];
        __shared__ unsigned short sFin[LSTRIDE];
        __shared__ int sCnt[257];
        __shared__ int sBankStart[33];
        __shared__ int sCur[32];

        const int c = blk;
        const int NITEMS = 2 * CELLS;               // 15100
        const int ITEMS  = (NITEMS + 255) / 256;    // 59
        int k0 = t * ITEMS;
        int k1 = min(k0 + ITEMS, NITEMS);

        int cnt = 0;
        for (int k = k0; k < k1; k++) {
            int part = (k >= CELLS) ? 1 : 0;
            int j = k - part * CELLS;
            int l = j / RR, rr = j % RR;
            float v = part ? mat[(c * CC + l) * RTOT + rr + 1]
                           : mat[(l * CC + c) * RTOT + rr + 1];
            cnt += (v != 0.0f) ? 1 : 0;
        }
        sCnt[t] = cnt;
        __syncthreads();
        if (t == 0) {
            int s = 0;
            for (int i = 0; i < 256; i++) { int x = sCnt[i]; sCnt[i] = s; s += x; }
            sCnt[256] = s;
        }
        __syncthreads();

        int pos = sCnt[t];
        for (int k = k0; k < k1; k++) {
            int part = (k >= CELLS) ? 1 : 0;
            int j = k - part * CELLS;
            int l = j / RR, rr = j % RR;
            float v = part ? mat[(c * CC + l) * RTOT + rr + 1]
                           : mat[(l * CC + c) * RTOT + rr + 1];
            if (v != 0.0f) {
                if (pos < LSTRIDE)
                    sRaw[pos] = (unsigned short)(part * CELLS + j);
                pos++;
            }
        }
        __syncthreads();

        int n = sCnt[256]; if (n > LSTRIDE) n = LSTRIDE;

        // Bucket entries by smem bank (idx mod 32), stable.
        if (t < 32) {
            int bc = 0;
            for (int i = 0; i < n; i++) bc += ((sRaw[i] & 31) == t) ? 1 : 0;
            sCur[t] = bc;
        }
        __syncthreads();
        if (t == 0) {
            int s = 0;
            for (int b2 = 0; b2 < 32; b2++) { sBankStart[b2] = s; s += sCur[b2]; }
            sBankStart[32] = s;
        }
        __syncthreads();
        if (t < 32) {
            int w = sBankStart[t];
            for (int i = 0; i < n; i++) {
                unsigned short e = sRaw[i];
                if ((e & 31) == t) sBank[w++] = e;
            }
            sCur[t] = sBankStart[t];
        }
        __syncthreads();

        // Greedy round-robin interleave: position k wants bank (k+c)&31.
        if (t == 0) {
            for (int k = 0; k < n; k++) {
                int d = (k + c) & 31;
                #pragma unroll 1
                while (sCur[d] >= sBankStart[d + 1]) d = (d + 1) & 31;
                sFin[k] = sBank[sCur[d]++];
            }
        }
        __syncthreads();

        int npad = (n + 7) & ~7;
        if (npad > (LSTRIDE & ~7)) npad = LSTRIDE & ~7;
        for (int i = t; i < npad; i += 256)
            g_list[c * LSTRIDE + i] = (i < n) ? sFin[i] : (unsigned short)GPAD;
        if (t == 0) g_cnt[c] = npad;
    } else {
        // ------- bucket branch (parallel stable counting sort) -------
        __shared__ int sL[PP];
        __shared__ int sC[CC];
        __shared__ int sS[CC + 1];

        const int b = blk - CC;
        if (b >= BB) return;
        if (t == 0 && b == 0) g_counter = 0;   // reset last-block counter

        sL[t] = labels[b * PP + t];
        for (int i = t; i < CC; i += 256) sC[i] = 0;
        __syncthreads();
        atomicAdd(&sC[sL[t]], 1);
        __syncthreads();
        if (t == 0) {
            int s = 0;
            for (int l = 0; l < CC; l++) { sS[l] = s; s += sC[l]; }
            sS[CC] = s;
        }
        __syncthreads();
        int lab = sL[t];
        int r = 0;
        for (int p = 0; p < t; p++) r += (sL[p] == lab) ? 1 : 0;
        g_perm[b][sS[lab] + r] = t;
        if (t < CC + 1) g_bstart[b][t] = sS[t];
    }
}

// ---------------------------------------------------------------------------
// Main kernel. One block per (b,q).
// Phase 1: label-bucketed aggregation of rel into G/G2 (smem, no atomics).
// Phase 2: sparse gather-sum per class (bank-staggered lists => conflict-free),
// then log-softmax + NLL. Last finished block reduces the mean.
// ---------------------------------------------------------------------------
extern __shared__ float dynsmem[];

__global__ __launch_bounds__(256) void main_kernel(const float* __restrict__ rel,
                                                   const int*  __restrict__ labels,
                                                   float* __restrict__ out) {
    float* G    = dynsmem;                        // [GTOT]
    int*   sAux = (int*)(G + GTOT);               // [408] : sStart(152) + sPerm(256)
    int*   sStart = sAux;
    int*   sPerm  = sAux + (CC + 1);
    float* sTheta = (float*)sAux;                 // alias (phase 2 only)
    float* sRed   = ((float*)sAux) + (CC + 1);    // alias (phase 2 only)
    __shared__ int sLast;

    const int b = blockIdx.x >> 8;
    const int q = blockIdx.x & 255;
    const int t = threadIdx.x;
    const int labq = labels[b * PP + q];

    if (t < CC + 1) sStart[t] = g_bstart[b][t];
    sPerm[t] = g_perm[b][t];
    if (t < 4) G[GPAD + t] = 0.0f;
    __syncthreads();

    // rel[((b*PP+p)*PP+qq)*RTOT + r]
    const float* colB = rel + ((long)(b * PP) * PP + q) * RTOT + 1;   // + p*PP*RTOT + rr
    const float* rowB = rel + ((long)(b * PP + q)) * PP * RTOT + 1;   // + p*RTOT + rr

    // Phase 1: lanes span consecutive rr within a class l -> coalesced loads.
    for (int j = t; j < CELLS; j += 256) {
        int l = j / RR, rr = j % RR;
        int s0 = sStart[l], s1 = sStart[l + 1];
        float sb = 0.0f, st = 0.0f;
        for (int i = s0; i < s1; i++) {
            int p = sPerm[i];
            sb += colB[p * (PP * RTOT) + rr];
            st += rowB[p * RTOT + rr];
        }
        G[j]         = sb;
        G[G2OFF + j] = st;
    }
    __syncthreads();

    // Diagonal correction: remove p == q contribution (r >= 1 only).
    if (t < RR) {
        float v = rowB[q * RTOT + t];
        int j = labq * RR + t;
        G[j]         -= v;
        G[G2OFF + j] -= v;
    }
    __syncthreads();

    // Phase 2: sparse gather-sum per class c = t (lists are bank-staggered).
    float theta = -INFINITY;
    if (t < CC) {
        int n = g_cnt[t];
        const uint4* lp = (const uint4*)&g_list[t * LSTRIDE];
        float a0 = 0.0f, a1 = 0.0f;
        int n8 = n >> 3;
        for (int i = 0; i < n8; i++) {
            uint4 v = lp[i];
            a0 += G[v.x & 0xFFFFu] + G[v.x >> 16];
            a1 += G[v.y & 0xFFFFu] + G[v.y >> 16];
            a0 += G[v.z & 0xFFFFu] + G[v.z >> 16];
            a1 += G[v.w & 0xFFFFu] + G[v.w >> 16];
        }
        theta = 0.25f * (a0 + a1);   // 0.5*(b+t), W=0.5 on r>=1
        sTheta[t] = theta;
    }

    // Block max
    float m = theta;
    #pragma unroll
    for (int o = 16; o; o >>= 1) m = fmaxf(m, __shfl_xor_sync(0xFFFFFFFFu, m, o));
    if ((t & 31) == 0) sRed[t >> 5] = m;
    __syncthreads();
    if (t == 0) {
        float mm = sRed[0];
        for (int i = 1; i < 8; i++) mm = fmaxf(mm, sRed[i]);
        sRed[8] = mm;
    }
    __syncthreads();
    m = sRed[8];

    // Block sum of exp
    float e = (t < CC) ? expf(theta - m) : 0.0f;
    #pragma unroll
    for (int o = 16; o; o >>= 1) e += __shfl_xor_sync(0xFFFFFFFFu, e, o);
    __syncthreads();
    if ((t & 31) == 0) sRed[t >> 5] = e;
    __syncthreads();

    if (t == 0) {
        float s = 0.0f;
        for (int i = 0; i < 8; i++) s += sRed[i];
        float lse = m + logf(s);
        g_loss[blockIdx.x] = lse - sTheta[labq];
        __threadfence();
        int old = atomicAdd(&g_counter, 1);
        sLast = (old == BB * PP - 1) ? 1 : 0;
    }
    __syncthreads();

    // Last block computes the deterministic mean.
    if (sLast) {
        __threadfence();
        float a = g_loss[t] + g_loss[t + 256] + g_loss[t + 512] + g_loss[t + 768];
        G[t] = a;
        __syncthreads();
        for (int o = 128; o; o >>= 1) {
            if (t < o) G[t] += G[t + o];
            __syncthreads();
        }
        if (t == 0) out[0] = G[0] * (1.0f / 1024.0f);
    }
}

// ---------------------------------------------------------------------------
extern "C" void kernel_launch(void* const* d_in, const int* in_sizes, int n_in,
                              void* d_out, int out_size) {
    const float* rel = nullptr;
    const float* mat = nullptr;
    const int*   lab = nullptr;
    for (int i = 0; i < n_in; i++) {
        switch (in_sizes[i]) {
            case BB * PP * PP * RTOT: rel = (const float*)d_in[i]; break;  // 13,369,344
            case CC * CC * RTOT:      mat = (const float*)d_in[i]; break;  // 1,162,701
            case BB * PP:             lab = (const int*)d_in[i];   break;  // 1,024
            default: break;  // roi_scores (unused), num_images (unused)
        }
    }

    const int smem_bytes = (GTOT + 408) * 4;  // 62,048 B
    cudaFuncSetAttribute(main_kernel, cudaFuncAttributeMaxDynamicSharedMemorySize, smem_bytes);

    prep_kernel<<<CC + BB, 256>>>(mat, lab);
    main_kernel<<<BB * PP, 256, smem_bytes>>>(rel, lab, (float*)d_out);
}